// round 15
// baseline (speedup 1.0000x reference)
#include <cuda_runtime.h>
#include <cuda_fp16.h>
#include <math.h>
#include <cfloat>
#include <cstdint>

#define B_   128
#define N_   8732
#define C_   512
#define H_   19
#define FG_  19
#define HID_ 4096

// ---------------------------------------------------------------------------
// scratch (device globals — no allocation allowed)
// ---------------------------------------------------------------------------
__device__ __align__(16) __half g_featH[B_*C_];
__device__ __align__(16) __half g_h1h[B_*HID_];
__device__ float g_h2[B_*HID_];
__device__ int   g_valid[B_];
__device__ uint32_t g_mask[B_*12];      // 361-bit in-box mask per batch
__device__ float g_part[4*B_*HID_];     // split-K partials (S<=4)
__device__ float g_w3t[FG_*HID_];       // w3 transposed

// ---------------------------------------------------------------------------
// helpers
// ---------------------------------------------------------------------------
#define MMA_F16(c, a, b0, b1)                                               \
    asm volatile("mma.sync.aligned.m16n8k16.row.col.f32.f16.f16.f32 "       \
        "{%0,%1,%2,%3}, {%4,%5,%6,%7}, {%8,%9}, {%0,%1,%2,%3};"             \
        : "+f"((c)[0]), "+f"((c)[1]), "+f"((c)[2]), "+f"((c)[3])            \
        : "r"((a)[0]), "r"((a)[1]), "r"((a)[2]), "r"((a)[3]),               \
          "r"(b0), "r"(b1))

#define LDSM_X4(r, addr)                                                    \
    asm volatile("ldmatrix.sync.aligned.m8n8.x4.shared.b16 "                \
        "{%0,%1,%2,%3}, [%4];"                                              \
        : "=r"((r)[0]), "=r"((r)[1]), "=r"((r)[2]), "=r"((r)[3])            \
        : "r"(addr) : "memory")

#define LDSM_X4T(r, addr)                                                   \
    asm volatile("ldmatrix.sync.aligned.m8n8.x4.trans.shared.b16 "          \
        "{%0,%1,%2,%3}, [%4];"                                              \
        : "=r"((r)[0]), "=r"((r)[1]), "=r"((r)[2]), "=r"((r)[3])            \
        : "r"(addr) : "memory")

#define CP_ASYNC16(dst, src)                                                \
    asm volatile("cp.async.cg.shared.global [%0], [%1], 16;"                \
        :: "r"(dst), "l"(src) : "memory")
#define CP_COMMIT()  asm volatile("cp.async.commit_group;" ::: "memory")
#define CP_WAIT1()   asm volatile("cp.async.wait_group 1;" ::: "memory")

__device__ __forceinline__ uint32_t pack2_f16(float x0, float x1)
{
    __half2 h = __floats2half2_rn(x0, x1);
    return *(uint32_t*)&h;
}

// ---------------------------------------------------------------------------
// Kernel 1: per-batch best car prior -> boxes/valid + 361-bit box bitmask
// ---------------------------------------------------------------------------
__global__ void best_prior_kernel(const float* __restrict__ loc,
                                  const float* __restrict__ conf,
                                  const float* __restrict__ priors,
                                  float* __restrict__ out)
{
    int b = blockIdx.x, tid = threadIdx.x;
    const float4* cb4 = (const float4*)(conf + (size_t)b * N_ * 2);
    const int NJ = N_ / 2;

    float best = -FLT_MAX;
    int   bidx = 0x7fffffff;
    int   anyc = 0;

    for (int j = tid; j < NJ; j += 256) {
        float4 c4 = cb4[j];
        int i0 = 2 * j, i1 = 2 * j + 1;
        if (c4.y > c4.x) {
            anyc = 1;
            float p1 = 1.0f / (1.0f + expf(c4.x - c4.y));
            if (p1 > best || (p1 == best && i0 < bidx)) { best = p1; bidx = i0; }
        }
        if (c4.w > c4.z) {
            anyc = 1;
            float p1 = 1.0f / (1.0f + expf(c4.z - c4.w));
            if (p1 > best || (p1 == best && i1 < bidx)) { best = p1; bidx = i1; }
        }
    }

    int has = __syncthreads_or(anyc);

    __shared__ float sv[256];
    __shared__ int   si[256];
    __shared__ int   sbins[4];
    __shared__ int   svalid;
    sv[tid] = best; si[tid] = bidx;
    __syncthreads();
    for (int s = 128; s > 0; s >>= 1) {
        if (tid < s) {
            float v2 = sv[tid+s]; int i2 = si[tid+s];
            if (v2 > sv[tid] || (v2 == sv[tid] && i2 < si[tid])) { sv[tid]=v2; si[tid]=i2; }
        }
        __syncthreads();
    }

    if (tid == 0) {
        float bx0=0.f,bx1=0.f,bx2=0.f,bx3=0.f;
        int v = 0;
        int n0=0,n1=0,n2=0,n3=0;
        if (has) {
            int idx = si[0];
            float p0 = priors[4*idx+0], p1p = priors[4*idx+1];
            float p2 = priors[4*idx+2], p3  = priors[4*idx+3];
            const float* l = loc + ((size_t)b * N_ + idx) * 4;
            float cx = p0 + l[0] * 0.1f * p2;
            float cy = p1p + l[1] * 0.1f * p3;
            float w  = p2 * expf(l[2] * 0.2f);
            float h  = p3 * expf(l[3] * 0.2f);
            float x1 = cx - 0.5f*w, y1 = cy - 0.5f*h;
            float x2 = x1 + w,      y2 = y1 + h;
            v = (x2 > x1) && (y2 > y1);
            bx0 = fminf(fmaxf(x1, 0.f), 1.f);
            bx1 = fminf(fmaxf(y1, 0.f), 1.f);
            bx2 = fminf(fmaxf(x2, 0.f), 1.f);
            bx3 = fminf(fmaxf(y2, 0.f), 1.f);
            const float step = (float)(300.0 / 19.0);
            float t;
            t = fminf(fmaxf(bx0*300.0f,0.f),300.f)/step; n0 = (int)floorf(fminf(fmaxf(t,0.f),18.f));
            t = fminf(fmaxf(bx1*300.0f,0.f),300.f)/step; n1 = (int)floorf(fminf(fmaxf(t,0.f),18.f));
            t = fminf(fmaxf(bx2*300.0f,0.f),300.f)/step; n2 = (int)floorf(fminf(fmaxf(t,0.f),18.f));
            t = fminf(fmaxf(bx3*300.0f,0.f),300.f)/step; n3 = (int)floorf(fminf(fmaxf(t,0.f),18.f));
        }
        out[2432 + b*4 + 0] = bx0;
        out[2432 + b*4 + 1] = bx1;
        out[2432 + b*4 + 2] = bx2;
        out[2432 + b*4 + 3] = bx3;
        out[2944 + b] = v ? 1.0f : 0.0f;
        g_valid[b]   = v;
        sbins[0] = n0; sbins[1] = n1; sbins[2] = n2; sbins[3] = n3;
        svalid = v;
    }
    __syncthreads();

    if (tid < 12) {
        uint32_t m = 0;
        if (svalid) {
            int x1 = sbins[0], y1 = sbins[1], x2 = sbins[2], y2 = sbins[3];
            #pragma unroll
            for (int j = 0; j < 32; j++) {
                int t = tid * 32 + j;
                if (t < H_ * H_) {
                    int y = t / H_;
                    int x = t - y * H_;
                    if (y >= y1 && y <= y2 && x >= x1 && x <= x2)
                        m |= (1u << j);
                }
            }
        }
        g_mask[b * 12 + tid] = m;
    }
}

// ---------------------------------------------------------------------------
// Kernel 2: masked global max pool -> g_featH [B, C] f16 (bitmask test)
// ---------------------------------------------------------------------------
__global__ void extract_kernel(const float* __restrict__ feats)
{
    int b     = blockIdx.x;
    int warp  = threadIdx.x >> 5;
    int lane  = threadIdx.x & 31;
    int cbase = blockIdx.y * 32 + warp * 4;

    if (!g_valid[b]) {
        if (lane < 4) g_featH[b*C_ + cbase + lane] = __float2half(0.f);
        return;
    }

    uint32_t mw[12];
    #pragma unroll
    for (int i = 0; i < 12; i++) mw[i] = g_mask[b * 12 + i];

    const float* f0 = feats + ((size_t)(b * C_ + cbase)) * (H_ * H_);

    float v[4][12];
    #pragma unroll
    for (int ch = 0; ch < 4; ch++) {
        const float* f = f0 + ch * (H_ * H_);
        #pragma unroll
        for (int i = 0; i < 11; i++) v[ch][i] = f[lane + 32 * i];
        v[ch][11] = (lane < 9) ? f[352 + lane] : -FLT_MAX;
    }

    #pragma unroll
    for (int ch = 0; ch < 4; ch++) {
        float m = -FLT_MAX;
        #pragma unroll
        for (int i = 0; i < 12; i++) {
            bool in = (mw[i] >> lane) & 1u;
            m = fmaxf(m, in ? v[ch][i] : -FLT_MAX);
        }
        #pragma unroll
        for (int o = 16; o; o >>= 1) m = fmaxf(m, __shfl_xor_sync(0xffffffffu, m, o));
        if (lane == 0) g_featH[b*C_ + cbase + ch] = __float2half_rn(m);
    }
}

// ---------------------------------------------------------------------------
// Kernel 3: hybrid GEMM, BN=32 / 128 threads / 4 warps -> 4 CTAs per SM.
//   part[split][128][HID_] = A[128, Ktot](f16) @ Bw[Ktot, HID_](f32)
//   BM=128, BN=32, BK=32; warp tile 32x32; double-buffered; A via cp.async.
// ---------------------------------------------------------------------------
#define A_PITCH   80               // bytes per A row (64 data + 16 pad)
#define B_PITCH   80               // bytes per B k-row (64 data + 16 pad)
#define A_BYTES   (128*A_PITCH)    // 10240
#define B_BYTES   (32*B_PITCH)     //  2560
#define BUF_BYTES (A_BYTES + B_BYTES)   // 12800
#define BUF_U32   (BUF_BYTES/4)
#define A_U32     (A_BYTES/4)

__global__ __launch_bounds__(128, 4)
void gemm_hyb_kernel(int Ktot, int KSPLIT,
                     const __half* __restrict__ Aw, const float* __restrict__ Bw,
                     float* __restrict__ part)
{
    extern __shared__ uint32_t sm[];

    const int tid  = threadIdx.x;
    const int wid  = tid >> 5;
    const int lane = tid & 31;
    const int gid  = lane >> 2;
    const int tig  = lane & 3;
    const int n0   = blockIdx.x * 32;
    const int ks   = blockIdx.y * KSPLIT;
    const int NCH  = KSPLIT >> 5;
    const int mbase = wid * 32;

    // B staging: thread owns (p, nq): k rows 2p,2p+1, col quad nq*4..+3
    const int bp_p  = tid >> 3;      // 0..15
    const int bp_nq = tid & 7;       // 0..7

    const uint32_t sbase = (uint32_t)__cvta_generic_to_shared(sm);

    const int l15  = lane & 15;
    const int lhi8 = (lane >> 4) * 8;
    const uint32_t a_off = (uint32_t)((mbase + l15) * A_PITCH + lhi8 * 2);
    const uint32_t b_off = (uint32_t)(l15 * B_PITCH + lhi8 * 2);

    float acc[2][4][4];
    #pragma unroll
    for (int i = 0; i < 2; i++)
        #pragma unroll
        for (int j = 0; j < 4; j++)
            #pragma unroll
            for (int q = 0; q < 4; q++) acc[i][j][q] = 0.f;

    float4 rb0, rb1;

    // A chunk (128x32 f16 = 8192B = 512x16B): 4 cp.async per thread
    #define ISSUE_A(buf, k0) do {                                           \
        uint32_t dA = sbase + (uint32_t)((buf) * BUF_BYTES);                \
        _Pragma("unroll")                                                   \
        for (int j = 0; j < 4; j++) {                                       \
            int idx = tid + j * 128;                                        \
            int row = idx >> 2, q = idx & 3;                                \
            const __half* src = Aw + (size_t)row * Ktot + (k0) + q * 8;     \
            CP_ASYNC16(dA + (uint32_t)(row * A_PITCH + q * 16), src);       \
        }                                                                   \
    } while (0)

    #define LOAD_B(k0) do {                                                 \
        const float* bp = Bw + (size_t)((k0) + 2 * bp_p) * HID_             \
                          + n0 + bp_nq * 4;                                 \
        rb0 = *(const float4*)bp;                                           \
        rb1 = *(const float4*)(bp + HID_);                                  \
    } while (0)

    #define STORE_B(buf) do {                                               \
        uint32_t* Bh = sm + (buf) * BUF_U32 + A_U32;                        \
        uint32_t h00 = pack2_f16(rb0.x, rb0.y), h01 = pack2_f16(rb0.z, rb0.w); \
        uint32_t h10 = pack2_f16(rb1.x, rb1.y), h11 = pack2_f16(rb1.z, rb1.w); \
        int r0 = (2*bp_p)     * (B_PITCH/4) + bp_nq * 2;                    \
        int r1 = (2*bp_p + 1) * (B_PITCH/4) + bp_nq * 2;                    \
        *(uint2*)&Bh[r0] = make_uint2(h00, h01);                            \
        *(uint2*)&Bh[r1] = make_uint2(h10, h11);                            \
    } while (0)

    // prologue
    ISSUE_A(0, ks);
    CP_COMMIT();
    if (NCH > 1) ISSUE_A(1, ks + 32);
    CP_COMMIT();
    LOAD_B(ks);
    STORE_B(0);
    if (NCH > 1) LOAD_B(ks + 32);
    CP_WAIT1();
    __syncthreads();

    for (int c = 0; c < NCH; c++) {
        const int buf = c & 1;
        const uint32_t AhA = sbase + (uint32_t)(buf * BUF_BYTES) + a_off;
        const uint32_t BhA = sbase + (uint32_t)(buf * BUF_BYTES + A_BYTES) + b_off;

        #pragma unroll
        for (int s = 0; s < 2; s++) {
            uint32_t a[2][4], bh[2][4];
            LDSM_X4(a[0], AhA + s * 32);
            LDSM_X4(a[1], AhA + s * 32 + 16 * A_PITCH);
            LDSM_X4T(bh[0], BhA + s * (16 * B_PITCH));
            LDSM_X4T(bh[1], BhA + s * (16 * B_PITCH) + 32);

            #pragma unroll
            for (int mt = 0; mt < 2; mt++) {
                #pragma unroll
                for (int ntp = 0; ntp < 2; ntp++) {
                    MMA_F16(acc[mt][2*ntp+0], a[mt], bh[ntp][0], bh[ntp][1]);
                    MMA_F16(acc[mt][2*ntp+1], a[mt], bh[ntp][2], bh[ntp][3]);
                }
            }
        }

        __syncthreads();
        if (c + 2 < NCH) ISSUE_A(buf, ks + (c + 2) * 32);
        CP_COMMIT();
        if (c + 1 < NCH) STORE_B(buf ^ 1);
        if (c + 2 < NCH) LOAD_B(ks + (c + 2) * 32);
        CP_WAIT1();
        __syncthreads();
    }

    // epilogue: partial sums
    #pragma unroll
    for (int mt = 0; mt < 2; mt++) {
        int row = mbase + mt * 16 + gid;
        float* base = part + ((size_t)blockIdx.y * 128 + row) * HID_ + n0;
        #pragma unroll
        for (int nt = 0; nt < 4; nt++) {
            float* d = base + nt * 8 + tig * 2;
            *(float2*)d               = make_float2(acc[mt][nt][0], acc[mt][nt][1]);
            *(float2*)(d + 8 * HID_)  = make_float2(acc[mt][nt][2], acc[mt][nt][3]);
        }
    }
    #undef ISSUE_A
    #undef LOAD_B
    #undef STORE_B
}

// ---------------------------------------------------------------------------
// Kernel 4a: split-K reduce + bias + relu -> f16 (2 float4 cols per thread)
// ---------------------------------------------------------------------------
__global__ void reduce_bias_h_kernel(int S, const float* __restrict__ part,
                                     const float* __restrict__ bias,
                                     __half* __restrict__ out)
{
    int t = blockIdx.x * 256 + threadIdx.x;
    const int MN = B_ * HID_;
    int base = t * 8;
    if (base >= MN) return;
    float4 s0 = make_float4(0.f,0.f,0.f,0.f), s1 = s0;
    for (int p = 0; p < S; p++) {
        const float* pp = part + (size_t)p * MN + base;
        float4 v0 = *(const float4*)pp;
        float4 v1 = *(const float4*)(pp + 4);
        s0.x += v0.x; s0.y += v0.y; s0.z += v0.z; s0.w += v0.w;
        s1.x += v1.x; s1.y += v1.y; s1.z += v1.z; s1.w += v1.w;
    }
    int n = base & (HID_ - 1);
    s0.x = fmaxf(s0.x + bias[n+0], 0.f);
    s0.y = fmaxf(s0.y + bias[n+1], 0.f);
    s0.z = fmaxf(s0.z + bias[n+2], 0.f);
    s0.w = fmaxf(s0.w + bias[n+3], 0.f);
    s1.x = fmaxf(s1.x + bias[n+4], 0.f);
    s1.y = fmaxf(s1.y + bias[n+5], 0.f);
    s1.z = fmaxf(s1.z + bias[n+6], 0.f);
    s1.w = fmaxf(s1.w + bias[n+7], 0.f);
    __half2 h0 = __floats2half2_rn(s0.x, s0.y);
    __half2 h1 = __floats2half2_rn(s0.z, s0.w);
    __half2 h2 = __floats2half2_rn(s1.x, s1.y);
    __half2 h3 = __floats2half2_rn(s1.z, s1.w);
    uint4 o;
    o.x = *(uint32_t*)&h0; o.y = *(uint32_t*)&h1;
    o.z = *(uint32_t*)&h2; o.w = *(uint32_t*)&h3;
    *(uint4*)(out + base) = o;
}

// ---------------------------------------------------------------------------
// Kernel 4b: split-K reduce + bias + relu -> f32 (2 float4 cols per thread)
// ---------------------------------------------------------------------------
__global__ void reduce_bias_f_kernel(int S, const float* __restrict__ part,
                                     const float* __restrict__ bias,
                                     float* __restrict__ out)
{
    int t = blockIdx.x * 256 + threadIdx.x;
    const int MN = B_ * HID_;
    int base = t * 8;
    if (base >= MN) return;
    float4 s0 = make_float4(0.f,0.f,0.f,0.f), s1 = s0;
    for (int p = 0; p < S; p++) {
        const float* pp = part + (size_t)p * MN + base;
        float4 v0 = *(const float4*)pp;
        float4 v1 = *(const float4*)(pp + 4);
        s0.x += v0.x; s0.y += v0.y; s0.z += v0.z; s0.w += v0.w;
        s1.x += v1.x; s1.y += v1.y; s1.z += v1.z; s1.w += v1.w;
    }
    int n = base & (HID_ - 1);
    s0.x = fmaxf(s0.x + bias[n+0], 0.f);
    s0.y = fmaxf(s0.y + bias[n+1], 0.f);
    s0.z = fmaxf(s0.z + bias[n+2], 0.f);
    s0.w = fmaxf(s0.w + bias[n+3], 0.f);
    s1.x = fmaxf(s1.x + bias[n+4], 0.f);
    s1.y = fmaxf(s1.y + bias[n+5], 0.f);
    s1.z = fmaxf(s1.z + bias[n+6], 0.f);
    s1.w = fmaxf(s1.w + bias[n+7], 0.f);
    *(float4*)(out + base)     = s0;
    *(float4*)(out + base + 4) = s1;
}

// ---------------------------------------------------------------------------
// Kernel 5a: transpose w3 [4096,19] -> w3t [19,4096]
// ---------------------------------------------------------------------------
__global__ void w3t_kernel(const float* __restrict__ w3, float* __restrict__ w3t)
{
    int k = blockIdx.x * 256 + threadIdx.x;
    if (k >= HID_) return;
    #pragma unroll
    for (int c = 0; c < FG_; c++)
        w3t[c * HID_ + k] = w3[k * FG_ + c];
}

// ---------------------------------------------------------------------------
// Kernel 5b: final FC  out[b,col] = dot(h2[b], w3t[col]) + b3[col]
// ---------------------------------------------------------------------------
__global__ void fc3_kernel(const float* __restrict__ A, const float* __restrict__ Wt,
                           const float* __restrict__ bias, float* __restrict__ out)
{
    int gw   = blockIdx.x * 8 + (threadIdx.x >> 5);
    int lane = threadIdx.x & 31;
    if (gw >= B_ * FG_) return;
    int b = gw / FG_, col = gw - b * FG_;

    const float4* a = (const float4*)(A  + (size_t)b   * HID_);
    const float4* w = (const float4*)(Wt + (size_t)col * HID_);
    float s = 0.f;
    #pragma unroll 4
    for (int i = lane; i < HID_/4; i += 32) {
        float4 av = a[i], wv = w[i];
        s += av.x*wv.x + av.y*wv.y + av.z*wv.z + av.w*wv.w;
    }
    #pragma unroll
    for (int o = 16; o; o >>= 1) s += __shfl_xor_sync(0xffffffffu, s, o);
    if (lane == 0) out[b * FG_ + col] = s + bias[col];
}

// ---------------------------------------------------------------------------
extern "C" void kernel_launch(void* const* d_in, const int* in_sizes, int n_in,
                              void* d_out, int out_size)
{
    const float* loc      = (const float*)d_in[0];
    const float* conf     = (const float*)d_in[1];
    const float* priors   = (const float*)d_in[2];
    const float* features = (const float*)d_in[3];
    const float* w1 = (const float*)d_in[4];
    const float* b1 = (const float*)d_in[5];
    const float* w2 = (const float*)d_in[6];
    const float* b2 = (const float*)d_in[7];
    const float* w3 = (const float*)d_in[8];
    const float* b3 = (const float*)d_in[9];
    float* out = (float*)d_out;

    void *pfH, *p1h, *p2, *ppart, *pw3t;
    cudaGetSymbolAddress(&pfH,   g_featH);
    cudaGetSymbolAddress(&p1h,   g_h1h);
    cudaGetSymbolAddress(&p2,    g_h2);
    cudaGetSymbolAddress(&ppart, g_part);
    cudaGetSymbolAddress(&pw3t,  g_w3t);

    best_prior_kernel<<<B_, 256>>>(loc, conf, priors, out);
    extract_kernel<<<dim3(B_, C_/32), 256>>>(features);
    w3t_kernel<<<HID_/256, 256>>>(w3, (float*)pw3t);

    // GEMM1: [128,512] @ [512,4096], split-K=4 (KSPLIT=128, NCH=4), 512 CTAs
    gemm_hyb_kernel<<<dim3(HID_/32, 4), 128, 2*BUF_BYTES>>>(C_, 128,
        (const __half*)pfH, w1, (float*)ppart);
    reduce_bias_h_kernel<<<B_*HID_/8/256, 256>>>(4,
        (const float*)ppart, b1, (__half*)p1h);

    // GEMM2: [128,4096] @ [4096,4096], split-K=4 (KSPLIT=1024, NCH=32), 512 CTAs
    gemm_hyb_kernel<<<dim3(HID_/32, 4), 128, 2*BUF_BYTES>>>(HID_, 1024,
        (const __half*)p1h, w2, (float*)ppart);
    reduce_bias_f_kernel<<<B_*HID_/8/256, 256>>>(4,
        (const float*)ppart, b2, (float*)p2);

    fc3_kernel<<<(B_*FG_ + 7)/8, 256>>>((const float*)p2, (const float*)pw3t, b3, out);
}

// round 16
// speedup vs baseline: 1.0647x; 1.0647x over previous
#include <cuda_runtime.h>
#include <cuda_fp16.h>
#include <math.h>
#include <cfloat>
#include <cstdint>

#define B_   128
#define N_   8732
#define C_   512
#define H_   19
#define FG_  19
#define HID_ 4096

// ---------------------------------------------------------------------------
// scratch (device globals — no allocation allowed)
// ---------------------------------------------------------------------------
__device__ __align__(16) __half g_featH[B_*C_];
__device__ __align__(16) __half g_h1h[B_*HID_];
__device__ float g_h2[B_*HID_];
__device__ int   g_valid[B_];
__device__ uint32_t g_mask[B_*12];      // 361-bit in-box mask per batch
__device__ float g_part[4*B_*HID_];     // split-K partials (S<=4)
__device__ float g_w3t[FG_*HID_];       // w3 transposed

// ---------------------------------------------------------------------------
// helpers
// ---------------------------------------------------------------------------
#define MMA_F16(c, a, b0, b1)                                               \
    asm volatile("mma.sync.aligned.m16n8k16.row.col.f32.f16.f16.f32 "       \
        "{%0,%1,%2,%3}, {%4,%5,%6,%7}, {%8,%9}, {%0,%1,%2,%3};"             \
        : "+f"((c)[0]), "+f"((c)[1]), "+f"((c)[2]), "+f"((c)[3])            \
        : "r"((a)[0]), "r"((a)[1]), "r"((a)[2]), "r"((a)[3]),               \
          "r"(b0), "r"(b1))

#define LDSM_X4(r, addr)                                                    \
    asm volatile("ldmatrix.sync.aligned.m8n8.x4.shared.b16 "                \
        "{%0,%1,%2,%3}, [%4];"                                              \
        : "=r"((r)[0]), "=r"((r)[1]), "=r"((r)[2]), "=r"((r)[3])            \
        : "r"(addr) : "memory")

#define LDSM_X4T(r, addr)                                                   \
    asm volatile("ldmatrix.sync.aligned.m8n8.x4.trans.shared.b16 "          \
        "{%0,%1,%2,%3}, [%4];"                                              \
        : "=r"((r)[0]), "=r"((r)[1]), "=r"((r)[2]), "=r"((r)[3])            \
        : "r"(addr) : "memory")

#define CP_ASYNC16(dst, src)                                                \
    asm volatile("cp.async.cg.shared.global [%0], [%1], 16;"                \
        :: "r"(dst), "l"(src) : "memory")
#define CP_COMMIT()  asm volatile("cp.async.commit_group;" ::: "memory")
#define CP_WAIT1()   asm volatile("cp.async.wait_group 1;" ::: "memory")

__device__ __forceinline__ uint32_t pack2_f16(float x0, float x1)
{
    __half2 h = __floats2half2_rn(x0, x1);
    return *(uint32_t*)&h;
}

// ---------------------------------------------------------------------------
// Kernel 1: per-batch best car prior -> boxes/valid + 361-bit box bitmask
// ---------------------------------------------------------------------------
__global__ void best_prior_kernel(const float* __restrict__ loc,
                                  const float* __restrict__ conf,
                                  const float* __restrict__ priors,
                                  float* __restrict__ out)
{
    int b = blockIdx.x, tid = threadIdx.x;
    const float4* cb4 = (const float4*)(conf + (size_t)b * N_ * 2);
    const int NJ = N_ / 2;

    float best = -FLT_MAX;
    int   bidx = 0x7fffffff;
    int   anyc = 0;

    for (int j = tid; j < NJ; j += 256) {
        float4 c4 = cb4[j];
        int i0 = 2 * j, i1 = 2 * j + 1;
        if (c4.y > c4.x) {
            anyc = 1;
            float p1 = 1.0f / (1.0f + expf(c4.x - c4.y));
            if (p1 > best || (p1 == best && i0 < bidx)) { best = p1; bidx = i0; }
        }
        if (c4.w > c4.z) {
            anyc = 1;
            float p1 = 1.0f / (1.0f + expf(c4.z - c4.w));
            if (p1 > best || (p1 == best && i1 < bidx)) { best = p1; bidx = i1; }
        }
    }

    int has = __syncthreads_or(anyc);

    __shared__ float sv[256];
    __shared__ int   si[256];
    __shared__ int   sbins[4];
    __shared__ int   svalid;
    sv[tid] = best; si[tid] = bidx;
    __syncthreads();
    for (int s = 128; s > 0; s >>= 1) {
        if (tid < s) {
            float v2 = sv[tid+s]; int i2 = si[tid+s];
            if (v2 > sv[tid] || (v2 == sv[tid] && i2 < si[tid])) { sv[tid]=v2; si[tid]=i2; }
        }
        __syncthreads();
    }

    if (tid == 0) {
        float bx0=0.f,bx1=0.f,bx2=0.f,bx3=0.f;
        int v = 0;
        int n0=0,n1=0,n2=0,n3=0;
        if (has) {
            int idx = si[0];
            float p0 = priors[4*idx+0], p1p = priors[4*idx+1];
            float p2 = priors[4*idx+2], p3  = priors[4*idx+3];
            const float* l = loc + ((size_t)b * N_ + idx) * 4;
            float cx = p0 + l[0] * 0.1f * p2;
            float cy = p1p + l[1] * 0.1f * p3;
            float w  = p2 * expf(l[2] * 0.2f);
            float h  = p3 * expf(l[3] * 0.2f);
            float x1 = cx - 0.5f*w, y1 = cy - 0.5f*h;
            float x2 = x1 + w,      y2 = y1 + h;
            v = (x2 > x1) && (y2 > y1);
            bx0 = fminf(fmaxf(x1, 0.f), 1.f);
            bx1 = fminf(fmaxf(y1, 0.f), 1.f);
            bx2 = fminf(fmaxf(x2, 0.f), 1.f);
            bx3 = fminf(fmaxf(y2, 0.f), 1.f);
            const float step = (float)(300.0 / 19.0);
            float t;
            t = fminf(fmaxf(bx0*300.0f,0.f),300.f)/step; n0 = (int)floorf(fminf(fmaxf(t,0.f),18.f));
            t = fminf(fmaxf(bx1*300.0f,0.f),300.f)/step; n1 = (int)floorf(fminf(fmaxf(t,0.f),18.f));
            t = fminf(fmaxf(bx2*300.0f,0.f),300.f)/step; n2 = (int)floorf(fminf(fmaxf(t,0.f),18.f));
            t = fminf(fmaxf(bx3*300.0f,0.f),300.f)/step; n3 = (int)floorf(fminf(fmaxf(t,0.f),18.f));
        }
        out[2432 + b*4 + 0] = bx0;
        out[2432 + b*4 + 1] = bx1;
        out[2432 + b*4 + 2] = bx2;
        out[2432 + b*4 + 3] = bx3;
        out[2944 + b] = v ? 1.0f : 0.0f;
        g_valid[b]   = v;
        sbins[0] = n0; sbins[1] = n1; sbins[2] = n2; sbins[3] = n3;
        svalid = v;
    }
    __syncthreads();

    if (tid < 12) {
        uint32_t m = 0;
        if (svalid) {
            int x1 = sbins[0], y1 = sbins[1], x2 = sbins[2], y2 = sbins[3];
            #pragma unroll
            for (int j = 0; j < 32; j++) {
                int t = tid * 32 + j;
                if (t < H_ * H_) {
                    int y = t / H_;
                    int x = t - y * H_;
                    if (y >= y1 && y <= y2 && x >= x1 && x <= x2)
                        m |= (1u << j);
                }
            }
        }
        g_mask[b * 12 + tid] = m;
    }
}

// ---------------------------------------------------------------------------
// Kernel 2: masked global max pool -> g_featH [B, C] f16 (bitmask test)
// ---------------------------------------------------------------------------
__global__ void extract_kernel(const float* __restrict__ feats)
{
    int b     = blockIdx.x;
    int warp  = threadIdx.x >> 5;
    int lane  = threadIdx.x & 31;
    int cbase = blockIdx.y * 32 + warp * 4;

    if (!g_valid[b]) {
        if (lane < 4) g_featH[b*C_ + cbase + lane] = __float2half(0.f);
        return;
    }

    uint32_t mw[12];
    #pragma unroll
    for (int i = 0; i < 12; i++) mw[i] = g_mask[b * 12 + i];

    const float* f0 = feats + ((size_t)(b * C_ + cbase)) * (H_ * H_);

    float v[4][12];
    #pragma unroll
    for (int ch = 0; ch < 4; ch++) {
        const float* f = f0 + ch * (H_ * H_);
        #pragma unroll
        for (int i = 0; i < 11; i++) v[ch][i] = f[lane + 32 * i];
        v[ch][11] = (lane < 9) ? f[352 + lane] : -FLT_MAX;
    }

    #pragma unroll
    for (int ch = 0; ch < 4; ch++) {
        float m = -FLT_MAX;
        #pragma unroll
        for (int i = 0; i < 12; i++) {
            bool in = (mw[i] >> lane) & 1u;
            m = fmaxf(m, in ? v[ch][i] : -FLT_MAX);
        }
        #pragma unroll
        for (int o = 16; o; o >>= 1) m = fmaxf(m, __shfl_xor_sync(0xffffffffu, m, o));
        if (lane == 0) g_featH[b*C_ + cbase + ch] = __float2half_rn(m);
    }
}

// ---------------------------------------------------------------------------
// Kernel 3: hybrid GEMM — A f16 via cp.async, B f32 fused-convert (depth-2
// register pipeline). BM=128, BN=64, BK=32; 8 warps; double-buffered SMEM.
//   FUSE=0: part[split][128][HID_] partial sums (split-K)
//   FUSE=1: out_h[128][HID_] = relu(A@B + bias) as f16 (single split)
// ---------------------------------------------------------------------------
#define A_PITCH   80
#define B_PITCH   144
#define A_BYTES   (128*A_PITCH)
#define B_BYTES   (32*B_PITCH)
#define BUF_BYTES (A_BYTES + B_BYTES)
#define BUF_U32   (BUF_BYTES/4)
#define A_U32     (A_BYTES/4)

template<bool FUSE>
__global__ __launch_bounds__(256, 2)
void gemm_hyb_kernel(int Ktot, int KSPLIT,
                     const __half* __restrict__ Aw, const float* __restrict__ Bw,
                     float* __restrict__ part,
                     const float* __restrict__ bias, __half* __restrict__ outh)
{
    extern __shared__ uint32_t sm[];

    const int tid  = threadIdx.x;
    const int wid  = tid >> 5;
    const int lane = tid & 31;
    const int gid  = lane >> 2;
    const int tig  = lane & 3;
    const int n0   = blockIdx.x * 64;
    const int ks   = blockIdx.y * KSPLIT;
    const int NCH  = KSPLIT >> 5;
    const int mbase = (wid & 3) * 32;
    const int nbase = (wid >> 2) * 32;

    const int bp_p  = tid >> 4;      // 0..15
    const int bp_nq = tid & 15;      // 0..15

    const uint32_t sbase = (uint32_t)__cvta_generic_to_shared(sm);

    const int l15  = lane & 15;
    const int lhi8 = (lane >> 4) * 8;
    const uint32_t a_off = (uint32_t)((mbase + l15) * A_PITCH + lhi8 * 2);
    const uint32_t b_off = (uint32_t)(l15 * B_PITCH + (nbase + lhi8) * 2);

    float acc[2][4][4];
    #pragma unroll
    for (int i = 0; i < 2; i++)
        #pragma unroll
        for (int j = 0; j < 4; j++)
            #pragma unroll
            for (int q = 0; q < 4; q++) acc[i][j][q] = 0.f;

    float4 rbs[2][2];                // [set][row 2p / 2p+1]

    #define ISSUE_A(buf, k0) do {                                           \
        uint32_t dA = sbase + (uint32_t)((buf) * BUF_BYTES);                \
        _Pragma("unroll")                                                   \
        for (int j = 0; j < 2; j++) {                                       \
            int idx = tid + j * 256;                                        \
            int row = idx >> 2, q = idx & 3;                                \
            const __half* src = Aw + (size_t)row * Ktot + (k0) + q * 8;     \
            CP_ASYNC16(dA + (uint32_t)(row * A_PITCH + q * 16), src);       \
        }                                                                   \
    } while (0)

    #define LOAD_B(set, k0) do {                                            \
        const float* bp = Bw + (size_t)((k0) + 2 * bp_p) * HID_             \
                          + n0 + bp_nq * 4;                                 \
        rbs[set][0] = *(const float4*)bp;                                   \
        rbs[set][1] = *(const float4*)(bp + HID_);                          \
    } while (0)

    #define STORE_B(buf, set) do {                                          \
        uint32_t* Bh = sm + (buf) * BUF_U32 + A_U32;                        \
        float4 r0 = rbs[set][0], r1 = rbs[set][1];                          \
        uint32_t h00 = pack2_f16(r0.x, r0.y), h01 = pack2_f16(r0.z, r0.w);  \
        uint32_t h10 = pack2_f16(r1.x, r1.y), h11 = pack2_f16(r1.z, r1.w);  \
        int q0 = (2*bp_p)     * (B_PITCH/4) + bp_nq * 2;                    \
        int q1 = (2*bp_p + 1) * (B_PITCH/4) + bp_nq * 2;                    \
        *(uint2*)&Bh[q0] = make_uint2(h00, h01);                            \
        *(uint2*)&Bh[q1] = make_uint2(h10, h11);                            \
    } while (0)

    // prologue (B reg pipeline depth 2)
    ISSUE_A(0, ks);
    CP_COMMIT();
    if (NCH > 1) ISSUE_A(1, ks + 32);
    CP_COMMIT();
    LOAD_B(0, ks);
    STORE_B(0, 0);
    if (NCH > 1) LOAD_B(1, ks + 32);
    if (NCH > 2) LOAD_B(0, ks + 64);
    CP_WAIT1();
    __syncthreads();

    for (int c = 0; c < NCH; c++) {
        const int buf = c & 1;
        const uint32_t AhA = sbase + (uint32_t)(buf * BUF_BYTES) + a_off;
        const uint32_t BhA = sbase + (uint32_t)(buf * BUF_BYTES + A_BYTES) + b_off;

        #pragma unroll
        for (int s = 0; s < 2; s++) {
            uint32_t a[2][4], bh[2][4];
            LDSM_X4(a[0], AhA + s * 32);
            LDSM_X4(a[1], AhA + s * 32 + 16 * A_PITCH);
            LDSM_X4T(bh[0], BhA + s * (16 * B_PITCH));
            LDSM_X4T(bh[1], BhA + s * (16 * B_PITCH) + 32);

            #pragma unroll
            for (int mt = 0; mt < 2; mt++) {
                #pragma unroll
                for (int ntp = 0; ntp < 2; ntp++) {
                    MMA_F16(acc[mt][2*ntp+0], a[mt], bh[ntp][0], bh[ntp][1]);
                    MMA_F16(acc[mt][2*ntp+1], a[mt], bh[ntp][2], bh[ntp][3]);
                }
            }
        }

        __syncthreads();
        if (c + 2 < NCH) ISSUE_A(buf, ks + (c + 2) * 32);
        CP_COMMIT();
        if (c + 1 < NCH) STORE_B(buf ^ 1, (c + 1) & 1);
        if (c + 3 < NCH) LOAD_B((c + 3) & 1, ks + (c + 3) * 32);
        CP_WAIT1();
        __syncthreads();
    }

    // epilogue
    #pragma unroll
    for (int mt = 0; mt < 2; mt++) {
        int row = mbase + mt * 16 + gid;
        if (FUSE) {
            __half* base = outh + (size_t)row * HID_ + n0 + nbase;
            #pragma unroll
            for (int nt = 0; nt < 4; nt++) {
                int col = n0 + nbase + nt * 8 + tig * 2;
                float b0 = bias[col], b1 = bias[col + 1];
                float v0 = fmaxf(acc[mt][nt][0] + b0, 0.f);
                float v1 = fmaxf(acc[mt][nt][1] + b1, 0.f);
                float v2 = fmaxf(acc[mt][nt][2] + b0, 0.f);
                float v3 = fmaxf(acc[mt][nt][3] + b1, 0.f);
                __half* d = base + nt * 8 + tig * 2;
                *(uint32_t*)d              = pack2_f16(v0, v1);
                *(uint32_t*)(d + 8 * HID_) = pack2_f16(v2, v3);
            }
        } else {
            float* base = part + ((size_t)blockIdx.y * 128 + row) * HID_ + n0 + nbase;
            #pragma unroll
            for (int nt = 0; nt < 4; nt++) {
                float* d = base + nt * 8 + tig * 2;
                *(float2*)d               = make_float2(acc[mt][nt][0], acc[mt][nt][1]);
                *(float2*)(d + 8 * HID_)  = make_float2(acc[mt][nt][2], acc[mt][nt][3]);
            }
        }
    }
    #undef ISSUE_A
    #undef LOAD_B
    #undef STORE_B
}

// ---------------------------------------------------------------------------
// Kernel 4: split-K reduce + bias + relu -> f32 (2 float4 cols per thread)
// ---------------------------------------------------------------------------
__global__ void reduce_bias_f_kernel(int S, const float* __restrict__ part,
                                     const float* __restrict__ bias,
                                     float* __restrict__ out)
{
    int t = blockIdx.x * 256 + threadIdx.x;
    const int MN = B_ * HID_;
    int base = t * 8;
    if (base >= MN) return;
    float4 s0 = make_float4(0.f,0.f,0.f,0.f), s1 = s0;
    for (int p = 0; p < S; p++) {
        const float* pp = part + (size_t)p * MN + base;
        float4 v0 = *(const float4*)pp;
        float4 v1 = *(const float4*)(pp + 4);
        s0.x += v0.x; s0.y += v0.y; s0.z += v0.z; s0.w += v0.w;
        s1.x += v1.x; s1.y += v1.y; s1.z += v1.z; s1.w += v1.w;
    }
    int n = base & (HID_ - 1);
    s0.x = fmaxf(s0.x + bias[n+0], 0.f);
    s0.y = fmaxf(s0.y + bias[n+1], 0.f);
    s0.z = fmaxf(s0.z + bias[n+2], 0.f);
    s0.w = fmaxf(s0.w + bias[n+3], 0.f);
    s1.x = fmaxf(s1.x + bias[n+4], 0.f);
    s1.y = fmaxf(s1.y + bias[n+5], 0.f);
    s1.z = fmaxf(s1.z + bias[n+6], 0.f);
    s1.w = fmaxf(s1.w + bias[n+7], 0.f);
    *(float4*)(out + base)     = s0;
    *(float4*)(out + base + 4) = s1;
}

// ---------------------------------------------------------------------------
// Kernel 5a: transpose w3 [4096,19] -> w3t [19,4096]
// ---------------------------------------------------------------------------
__global__ void w3t_kernel(const float* __restrict__ w3, float* __restrict__ w3t)
{
    int k = blockIdx.x * 256 + threadIdx.x;
    if (k >= HID_) return;
    #pragma unroll
    for (int c = 0; c < FG_; c++)
        w3t[c * HID_ + k] = w3[k * FG_ + c];
}

// ---------------------------------------------------------------------------
// Kernel 5b: final FC  out[b,col] = dot(h2[b], w3t[col]) + b3[col]
// ---------------------------------------------------------------------------
__global__ void fc3_kernel(const float* __restrict__ A, const float* __restrict__ Wt,
                           const float* __restrict__ bias, float* __restrict__ out)
{
    int gw   = blockIdx.x * 8 + (threadIdx.x >> 5);
    int lane = threadIdx.x & 31;
    if (gw >= B_ * FG_) return;
    int b = gw / FG_, col = gw - b * FG_;

    const float4* a = (const float4*)(A  + (size_t)b   * HID_);
    const float4* w = (const float4*)(Wt + (size_t)col * HID_);
    float s = 0.f;
    #pragma unroll 4
    for (int i = lane; i < HID_/4; i += 32) {
        float4 av = a[i], wv = w[i];
        s += av.x*wv.x + av.y*wv.y + av.z*wv.z + av.w*wv.w;
    }
    #pragma unroll
    for (int o = 16; o; o >>= 1) s += __shfl_xor_sync(0xffffffffu, s, o);
    if (lane == 0) out[b * FG_ + col] = s + bias[col];
}

// ---------------------------------------------------------------------------
extern "C" void kernel_launch(void* const* d_in, const int* in_sizes, int n_in,
                              void* d_out, int out_size)
{
    const float* loc      = (const float*)d_in[0];
    const float* conf     = (const float*)d_in[1];
    const float* priors   = (const float*)d_in[2];
    const float* features = (const float*)d_in[3];
    const float* w1 = (const float*)d_in[4];
    const float* b1 = (const float*)d_in[5];
    const float* w2 = (const float*)d_in[6];
    const float* b2 = (const float*)d_in[7];
    const float* w3 = (const float*)d_in[8];
    const float* b3 = (const float*)d_in[9];
    float* out = (float*)d_out;

    void *pfH, *p1h, *p2, *ppart, *pw3t;
    cudaGetSymbolAddress(&pfH,   g_featH);
    cudaGetSymbolAddress(&p1h,   g_h1h);
    cudaGetSymbolAddress(&p2,    g_h2);
    cudaGetSymbolAddress(&ppart, g_part);
    cudaGetSymbolAddress(&pw3t,  g_w3t);

    best_prior_kernel<<<B_, 256>>>(loc, conf, priors, out);              // 1
    extract_kernel<<<dim3(B_, C_/32), 256>>>(features);                  // 2

    // GEMM1 fused: [128,512]@[512,4096] + bias + relu -> f16 h1h (no reduce)
    gemm_hyb_kernel<true><<<dim3(HID_/64, 1), 256, 2*BUF_BYTES>>>(       // 3
        C_, C_, (const __half*)pfH, w1, nullptr, b1, (__half*)p1h);

    // GEMM2: [128,4096]@[4096,4096], split-K=4 (profiled as launch #4)
    gemm_hyb_kernel<false><<<dim3(HID_/64, 4), 256, 2*BUF_BYTES>>>(      // 4
        HID_, 1024, (const __half*)p1h, w2, (float*)ppart, nullptr, nullptr);
    reduce_bias_f_kernel<<<B_*HID_/8/256, 256>>>(4,                      // 5
        (const float*)ppart, b2, (float*)p2);

    w3t_kernel<<<HID_/256, 256>>>(w3, (float*)pw3t);                     // 6
    fc3_kernel<<<(B_*FG_ + 7)/8, 256>>>((const float*)p2,                // 7
        (const float*)pw3t, b3, out);
}

// round 17
// speedup vs baseline: 1.1736x; 1.1023x over previous
#include <cuda_runtime.h>
#include <cuda_fp16.h>
#include <math.h>
#include <cfloat>
#include <cstdint>

#define B_   128
#define N_   8732
#define C_   512
#define H_   19
#define FG_  19
#define HID_ 4096

// ---------------------------------------------------------------------------
// scratch (device globals — no allocation allowed)
// ---------------------------------------------------------------------------
__device__ __align__(16) __half g_featH[B_*C_];
__device__ __align__(16) __half g_h1h[B_*HID_];
__device__ float g_h2[B_*HID_];
__device__ int   g_valid[B_];
__device__ int   g_bins[B_*4];
__device__ float g_part[4*B_*HID_];     // split-K partials (S<=4)
__device__ float g_w3t[FG_*HID_];       // w3 transposed

// ---------------------------------------------------------------------------
// helpers
// ---------------------------------------------------------------------------
#define MMA_F16(c, a, b0, b1)                                               \
    asm volatile("mma.sync.aligned.m16n8k16.row.col.f32.f16.f16.f32 "       \
        "{%0,%1,%2,%3}, {%4,%5,%6,%7}, {%8,%9}, {%0,%1,%2,%3};"             \
        : "+f"((c)[0]), "+f"((c)[1]), "+f"((c)[2]), "+f"((c)[3])            \
        : "r"((a)[0]), "r"((a)[1]), "r"((a)[2]), "r"((a)[3]),               \
          "r"(b0), "r"(b1))

#define LDSM_X4(r, addr)                                                    \
    asm volatile("ldmatrix.sync.aligned.m8n8.x4.shared.b16 "                \
        "{%0,%1,%2,%3}, [%4];"                                              \
        : "=r"((r)[0]), "=r"((r)[1]), "=r"((r)[2]), "=r"((r)[3])            \
        : "r"(addr) : "memory")

#define LDSM_X4T(r, addr)                                                   \
    asm volatile("ldmatrix.sync.aligned.m8n8.x4.trans.shared.b16 "          \
        "{%0,%1,%2,%3}, [%4];"                                              \
        : "=r"((r)[0]), "=r"((r)[1]), "=r"((r)[2]), "=r"((r)[3])            \
        : "r"(addr) : "memory")

#define CP_ASYNC16(dst, src)                                                \
    asm volatile("cp.async.cg.shared.global [%0], [%1], 16;"                \
        :: "r"(dst), "l"(src) : "memory")
#define CP_COMMIT()  asm volatile("cp.async.commit_group;" ::: "memory")
#define CP_WAIT1()   asm volatile("cp.async.wait_group 1;" ::: "memory")

__device__ __forceinline__ uint32_t pack2_f16(float x0, float x1)
{
    __half2 h = __floats2half2_rn(x0, x1);
    return *(uint32_t*)&h;
}

// ---------------------------------------------------------------------------
// Kernel 1: per-batch best car prior -> boxes/valid + bins
// ---------------------------------------------------------------------------
__global__ void best_prior_kernel(const float* __restrict__ loc,
                                  const float* __restrict__ conf,
                                  const float* __restrict__ priors,
                                  float* __restrict__ out)
{
    int b = blockIdx.x, tid = threadIdx.x;
    const float4* cb4 = (const float4*)(conf + (size_t)b * N_ * 2);
    const int NJ = N_ / 2;

    float best = -FLT_MAX;
    int   bidx = 0x7fffffff;
    int   anyc = 0;

    for (int j = tid; j < NJ; j += 256) {
        float4 c4 = cb4[j];
        int i0 = 2 * j, i1 = 2 * j + 1;
        if (c4.y > c4.x) {
            anyc = 1;
            float p1 = 1.0f / (1.0f + expf(c4.x - c4.y));
            if (p1 > best || (p1 == best && i0 < bidx)) { best = p1; bidx = i0; }
        }
        if (c4.w > c4.z) {
            anyc = 1;
            float p1 = 1.0f / (1.0f + expf(c4.z - c4.w));
            if (p1 > best || (p1 == best && i1 < bidx)) { best = p1; bidx = i1; }
        }
    }

    int has = __syncthreads_or(anyc);

    __shared__ float sv[256];
    __shared__ int   si[256];
    sv[tid] = best; si[tid] = bidx;
    __syncthreads();
    for (int s = 128; s > 0; s >>= 1) {
        if (tid < s) {
            float v2 = sv[tid+s]; int i2 = si[tid+s];
            if (v2 > sv[tid] || (v2 == sv[tid] && i2 < si[tid])) { sv[tid]=v2; si[tid]=i2; }
        }
        __syncthreads();
    }

    if (tid == 0) {
        float bx0=0.f,bx1=0.f,bx2=0.f,bx3=0.f;
        int v = 0;
        int n0=0,n1=0,n2=0,n3=0;
        if (has) {
            int idx = si[0];
            float p0 = priors[4*idx+0], p1p = priors[4*idx+1];
            float p2 = priors[4*idx+2], p3  = priors[4*idx+3];
            const float* l = loc + ((size_t)b * N_ + idx) * 4;
            float cx = p0 + l[0] * 0.1f * p2;
            float cy = p1p + l[1] * 0.1f * p3;
            float w  = p2 * expf(l[2] * 0.2f);
            float h  = p3 * expf(l[3] * 0.2f);
            float x1 = cx - 0.5f*w, y1 = cy - 0.5f*h;
            float x2 = x1 + w,      y2 = y1 + h;
            v = (x2 > x1) && (y2 > y1);
            bx0 = fminf(fmaxf(x1, 0.f), 1.f);
            bx1 = fminf(fmaxf(y1, 0.f), 1.f);
            bx2 = fminf(fmaxf(x2, 0.f), 1.f);
            bx3 = fminf(fmaxf(y2, 0.f), 1.f);
            const float step = (float)(300.0 / 19.0);
            float t;
            t = fminf(fmaxf(bx0*300.0f,0.f),300.f)/step; n0 = (int)floorf(fminf(fmaxf(t,0.f),18.f));
            t = fminf(fmaxf(bx1*300.0f,0.f),300.f)/step; n1 = (int)floorf(fminf(fmaxf(t,0.f),18.f));
            t = fminf(fmaxf(bx2*300.0f,0.f),300.f)/step; n2 = (int)floorf(fminf(fmaxf(t,0.f),18.f));
            t = fminf(fmaxf(bx3*300.0f,0.f),300.f)/step; n3 = (int)floorf(fminf(fmaxf(t,0.f),18.f));
        }
        out[2432 + b*4 + 0] = bx0;
        out[2432 + b*4 + 1] = bx1;
        out[2432 + b*4 + 2] = bx2;
        out[2432 + b*4 + 3] = bx3;
        out[2944 + b] = v ? 1.0f : 0.0f;
        g_valid[b]    = v;
        g_bins[b*4+0] = n0; g_bins[b*4+1] = n1;
        g_bins[b*4+2] = n2; g_bins[b*4+3] = n3;
    }
}

// ---------------------------------------------------------------------------
// Kernel 2: masked max pool, BOX-RESTRICTED reads -> g_featH [B, C] f16
// one warp = 2 channels; lanes span box columns, 19 predicated row loads
// ---------------------------------------------------------------------------
__global__ void extract_kernel(const float* __restrict__ feats)
{
    int b     = blockIdx.x;
    int warp  = threadIdx.x >> 5;
    int lane  = threadIdx.x & 31;
    int cbase = blockIdx.y * 16 + warp * 2;

    if (!g_valid[b]) {
        if (lane < 2) g_featH[b*C_ + cbase + lane] = __float2half(0.f);
        return;
    }

    int x1 = g_bins[b*4+0], y1 = g_bins[b*4+1];
    int x2 = g_bins[b*4+2], y2 = g_bins[b*4+3];

    const float* f0 = feats + ((size_t)(b * C_ + cbase)) * (H_ * H_);
    const float* f1 = f0 + H_ * H_;

    bool lact = lane <= (x2 - x1);       // lane maps to x = x1 + lane
    int  xo   = x1 + lane;

    float m0 = -FLT_MAX, m1 = -FLT_MAX;
    #pragma unroll
    for (int iy = 0; iy < H_; iy++) {
        int y = y1 + iy;
        bool act = lact & (y <= y2);
        int off = y * H_ + xo;
        float v0 = act ? f0[off] : -FLT_MAX;
        float v1 = act ? f1[off] : -FLT_MAX;
        m0 = fmaxf(m0, v0);
        m1 = fmaxf(m1, v1);
    }
    #pragma unroll
    for (int o = 16; o; o >>= 1) {
        m0 = fmaxf(m0, __shfl_xor_sync(0xffffffffu, m0, o));
        m1 = fmaxf(m1, __shfl_xor_sync(0xffffffffu, m1, o));
    }
    if (lane == 0) {
        g_featH[b*C_ + cbase + 0] = __float2half_rn(m0);
        g_featH[b*C_ + cbase + 1] = __float2half_rn(m1);
    }
}

// ---------------------------------------------------------------------------
// Kernel 3: hybrid GEMM — A f16 via cp.async, B f32 fused-convert (depth-2
// register pipeline). BM=128, BN=64, BK=32; 8 warps; double-buffered SMEM.
//   FUSE=0: part[split][128][HID_] partial sums (split-K)
//   FUSE=1: out_h[128][HID_] = relu(A@B + bias) as f16 (single split)
// ---------------------------------------------------------------------------
#define A_PITCH   80
#define B_PITCH   144
#define A_BYTES   (128*A_PITCH)
#define B_BYTES   (32*B_PITCH)
#define BUF_BYTES (A_BYTES + B_BYTES)
#define BUF_U32   (BUF_BYTES/4)
#define A_U32     (A_BYTES/4)

template<bool FUSE>
__global__ __launch_bounds__(256, 2)
void gemm_hyb_kernel(int Ktot, int KSPLIT,
                     const __half* __restrict__ Aw, const float* __restrict__ Bw,
                     float* __restrict__ part,
                     const float* __restrict__ bias, __half* __restrict__ outh)
{
    extern __shared__ uint32_t sm[];

    const int tid  = threadIdx.x;
    const int wid  = tid >> 5;
    const int lane = tid & 31;
    const int gid  = lane >> 2;
    const int tig  = lane & 3;
    const int n0   = blockIdx.x * 64;
    const int ks   = blockIdx.y * KSPLIT;
    const int NCH  = KSPLIT >> 5;
    const int mbase = (wid & 3) * 32;
    const int nbase = (wid >> 2) * 32;

    const int bp_p  = tid >> 4;
    const int bp_nq = tid & 15;

    const uint32_t sbase = (uint32_t)__cvta_generic_to_shared(sm);

    const int l15  = lane & 15;
    const int lhi8 = (lane >> 4) * 8;
    const uint32_t a_off = (uint32_t)((mbase + l15) * A_PITCH + lhi8 * 2);
    const uint32_t b_off = (uint32_t)(l15 * B_PITCH + (nbase + lhi8) * 2);

    float acc[2][4][4];
    #pragma unroll
    for (int i = 0; i < 2; i++)
        #pragma unroll
        for (int j = 0; j < 4; j++)
            #pragma unroll
            for (int q = 0; q < 4; q++) acc[i][j][q] = 0.f;

    float4 rbs[2][2];

    #define ISSUE_A(buf, k0) do {                                           \
        uint32_t dA = sbase + (uint32_t)((buf) * BUF_BYTES);                \
        _Pragma("unroll")                                                   \
        for (int j = 0; j < 2; j++) {                                       \
            int idx = tid + j * 256;                                        \
            int row = idx >> 2, q = idx & 3;                                \
            const __half* src = Aw + (size_t)row * Ktot + (k0) + q * 8;     \
            CP_ASYNC16(dA + (uint32_t)(row * A_PITCH + q * 16), src);       \
        }                                                                   \
    } while (0)

    #define LOAD_B(set, k0) do {                                            \
        const float* bp = Bw + (size_t)((k0) + 2 * bp_p) * HID_             \
                          + n0 + bp_nq * 4;                                 \
        rbs[set][0] = *(const float4*)bp;                                   \
        rbs[set][1] = *(const float4*)(bp + HID_);                          \
    } while (0)

    #define STORE_B(buf, set) do {                                          \
        uint32_t* Bh = sm + (buf) * BUF_U32 + A_U32;                        \
        float4 r0 = rbs[set][0], r1 = rbs[set][1];                          \
        uint32_t h00 = pack2_f16(r0.x, r0.y), h01 = pack2_f16(r0.z, r0.w);  \
        uint32_t h10 = pack2_f16(r1.x, r1.y), h11 = pack2_f16(r1.z, r1.w);  \
        int q0 = (2*bp_p)     * (B_PITCH/4) + bp_nq * 2;                    \
        int q1 = (2*bp_p + 1) * (B_PITCH/4) + bp_nq * 2;                    \
        *(uint2*)&Bh[q0] = make_uint2(h00, h01);                            \
        *(uint2*)&Bh[q1] = make_uint2(h10, h11);                            \
    } while (0)

    ISSUE_A(0, ks);
    CP_COMMIT();
    if (NCH > 1) ISSUE_A(1, ks + 32);
    CP_COMMIT();
    LOAD_B(0, ks);
    STORE_B(0, 0);
    if (NCH > 1) LOAD_B(1, ks + 32);
    if (NCH > 2) LOAD_B(0, ks + 64);
    CP_WAIT1();
    __syncthreads();

    for (int c = 0; c < NCH; c++) {
        const int buf = c & 1;
        const uint32_t AhA = sbase + (uint32_t)(buf * BUF_BYTES) + a_off;
        const uint32_t BhA = sbase + (uint32_t)(buf * BUF_BYTES + A_BYTES) + b_off;

        #pragma unroll
        for (int s = 0; s < 2; s++) {
            uint32_t a[2][4], bh[2][4];
            LDSM_X4(a[0], AhA + s * 32);
            LDSM_X4(a[1], AhA + s * 32 + 16 * A_PITCH);
            LDSM_X4T(bh[0], BhA + s * (16 * B_PITCH));
            LDSM_X4T(bh[1], BhA + s * (16 * B_PITCH) + 32);

            #pragma unroll
            for (int mt = 0; mt < 2; mt++) {
                #pragma unroll
                for (int ntp = 0; ntp < 2; ntp++) {
                    MMA_F16(acc[mt][2*ntp+0], a[mt], bh[ntp][0], bh[ntp][1]);
                    MMA_F16(acc[mt][2*ntp+1], a[mt], bh[ntp][2], bh[ntp][3]);
                }
            }
        }

        __syncthreads();
        if (c + 2 < NCH) ISSUE_A(buf, ks + (c + 2) * 32);
        CP_COMMIT();
        if (c + 1 < NCH) STORE_B(buf ^ 1, (c + 1) & 1);
        if (c + 3 < NCH) LOAD_B((c + 3) & 1, ks + (c + 3) * 32);
        CP_WAIT1();
        __syncthreads();
    }

    #pragma unroll
    for (int mt = 0; mt < 2; mt++) {
        int row = mbase + mt * 16 + gid;
        if (FUSE) {
            __half* base = outh + (size_t)row * HID_ + n0 + nbase;
            #pragma unroll
            for (int nt = 0; nt < 4; nt++) {
                int col = n0 + nbase + nt * 8 + tig * 2;
                float b0 = bias[col], b1 = bias[col + 1];
                float v0 = fmaxf(acc[mt][nt][0] + b0, 0.f);
                float v1 = fmaxf(acc[mt][nt][1] + b1, 0.f);
                float v2 = fmaxf(acc[mt][nt][2] + b0, 0.f);
                float v3 = fmaxf(acc[mt][nt][3] + b1, 0.f);
                __half* d = base + nt * 8 + tig * 2;
                *(uint32_t*)d              = pack2_f16(v0, v1);
                *(uint32_t*)(d + 8 * HID_) = pack2_f16(v2, v3);
            }
        } else {
            float* base = part + ((size_t)blockIdx.y * 128 + row) * HID_ + n0 + nbase;
            #pragma unroll
            for (int nt = 0; nt < 4; nt++) {
                float* d = base + nt * 8 + tig * 2;
                *(float2*)d               = make_float2(acc[mt][nt][0], acc[mt][nt][1]);
                *(float2*)(d + 8 * HID_)  = make_float2(acc[mt][nt][2], acc[mt][nt][3]);
            }
        }
    }
    #undef ISSUE_A
    #undef LOAD_B
    #undef STORE_B
}

// ---------------------------------------------------------------------------
// Kernel 4: split-K reduce + bias + relu -> f32 (2 float4 cols per thread)
// ---------------------------------------------------------------------------
__global__ void reduce_bias_f_kernel(int S, const float* __restrict__ part,
                                     const float* __restrict__ bias,
                                     float* __restrict__ out)
{
    int t = blockIdx.x * 256 + threadIdx.x;
    const int MN = B_ * HID_;
    int base = t * 8;
    if (base >= MN) return;
    float4 s0 = make_float4(0.f,0.f,0.f,0.f), s1 = s0;
    for (int p = 0; p < S; p++) {
        const float* pp = part + (size_t)p * MN + base;
        float4 v0 = *(const float4*)pp;
        float4 v1 = *(const float4*)(pp + 4);
        s0.x += v0.x; s0.y += v0.y; s0.z += v0.z; s0.w += v0.w;
        s1.x += v1.x; s1.y += v1.y; s1.z += v1.z; s1.w += v1.w;
    }
    int n = base & (HID_ - 1);
    s0.x = fmaxf(s0.x + bias[n+0], 0.f);
    s0.y = fmaxf(s0.y + bias[n+1], 0.f);
    s0.z = fmaxf(s0.z + bias[n+2], 0.f);
    s0.w = fmaxf(s0.w + bias[n+3], 0.f);
    s1.x = fmaxf(s1.x + bias[n+4], 0.f);
    s1.y = fmaxf(s1.y + bias[n+5], 0.f);
    s1.z = fmaxf(s1.z + bias[n+6], 0.f);
    s1.w = fmaxf(s1.w + bias[n+7], 0.f);
    *(float4*)(out + base)     = s0;
    *(float4*)(out + base + 4) = s1;
}

// ---------------------------------------------------------------------------
// Kernel 5a: transpose w3 [4096,19] -> w3t [19,4096]
// ---------------------------------------------------------------------------
__global__ void w3t_kernel(const float* __restrict__ w3, float* __restrict__ w3t)
{
    int k = blockIdx.x * 256 + threadIdx.x;
    if (k >= HID_) return;
    #pragma unroll
    for (int c = 0; c < FG_; c++)
        w3t[c * HID_ + k] = w3[k * FG_ + c];
}

// ---------------------------------------------------------------------------
// Kernel 5b: final FC  out[b,col] = dot(h2[b], w3t[col]) + b3[col]
// ---------------------------------------------------------------------------
__global__ void fc3_kernel(const float* __restrict__ A, const float* __restrict__ Wt,
                           const float* __restrict__ bias, float* __restrict__ out)
{
    int gw   = blockIdx.x * 8 + (threadIdx.x >> 5);
    int lane = threadIdx.x & 31;
    if (gw >= B_ * FG_) return;
    int b = gw / FG_, col = gw - b * FG_;

    const float4* a = (const float4*)(A  + (size_t)b   * HID_);
    const float4* w = (const float4*)(Wt + (size_t)col * HID_);
    float s = 0.f;
    #pragma unroll 4
    for (int i = lane; i < HID_/4; i += 32) {
        float4 av = a[i], wv = w[i];
        s += av.x*wv.x + av.y*wv.y + av.z*wv.z + av.w*wv.w;
    }
    #pragma unroll
    for (int o = 16; o; o >>= 1) s += __shfl_xor_sync(0xffffffffu, s, o);
    if (lane == 0) out[b * FG_ + col] = s + bias[col];
}

// ---------------------------------------------------------------------------
extern "C" void kernel_launch(void* const* d_in, const int* in_sizes, int n_in,
                              void* d_out, int out_size)
{
    const float* loc      = (const float*)d_in[0];
    const float* conf     = (const float*)d_in[1];
    const float* priors   = (const float*)d_in[2];
    const float* features = (const float*)d_in[3];
    const float* w1 = (const float*)d_in[4];
    const float* b1 = (const float*)d_in[5];
    const float* w2 = (const float*)d_in[6];
    const float* b2 = (const float*)d_in[7];
    const float* w3 = (const float*)d_in[8];
    const float* b3 = (const float*)d_in[9];
    float* out = (float*)d_out;

    void *pfH, *p1h, *p2, *ppart, *pw3t;
    cudaGetSymbolAddress(&pfH,   g_featH);
    cudaGetSymbolAddress(&p1h,   g_h1h);
    cudaGetSymbolAddress(&p2,    g_h2);
    cudaGetSymbolAddress(&ppart, g_part);
    cudaGetSymbolAddress(&pw3t,  g_w3t);

    best_prior_kernel<<<B_, 256>>>(loc, conf, priors, out);              // 1
    extract_kernel<<<dim3(B_, C_/16), 256>>>(features);                  // 2

    // GEMM1 fused: [128,512]@[512,4096] + bias + relu -> f16 h1h
    gemm_hyb_kernel<true><<<dim3(HID_/64, 1), 256, 2*BUF_BYTES>>>(       // 3
        C_, C_, (const __half*)pfH, w1, nullptr, b1, (__half*)p1h);

    // GEMM2: [128,4096]@[4096,4096], split-K=4 (profiled as launch #4)
    gemm_hyb_kernel<false><<<dim3(HID_/64, 4), 256, 2*BUF_BYTES>>>(      // 4
        HID_, 1024, (const __half*)p1h, w2, (float*)ppart, nullptr, nullptr);
    reduce_bias_f_kernel<<<B_*HID_/8/256, 256>>>(4,                      // 5
        (const float*)ppart, b2, (float*)p2);

    w3t_kernel<<<HID_/256, 256>>>(w3, (float*)pw3t);                     // 6
    fc3_kernel<<<(B_*FG_ + 7)/8, 256>>>((const float*)p2,                // 7
        (const float*)pw3t, b3, out);
}